// round 5
// baseline (speedup 1.0000x reference)
#include <cuda_runtime.h>

// Problem constants
#define Bz 32
#define Sz 512
#define Hz 1024
#define Lz 2
#define G4 4096                 // 4*Hz
#define BH (Bz*Hz)              // 32768
#define ROWS (Sz*Bz)            // 16384
#define MAIN (Bz*Sz*Hz)         // 16777216
#define NBLK 128

// Static scratch (no runtime allocation allowed)
__device__ float    g_G[(size_t)ROWS * G4];    // x-projection + biases, [row=t*32+b][4H]
__device__ float    g_seq[(size_t)ROWS * Hz];  // layer-0 hidden outputs, [row][H]
__device__ float    g_h[Lz * 2 * BH];          // double-buffered h state per layer
__device__ float    g_c[Lz * BH];              // c state per layer
__device__ unsigned g_flags[Lz * Sz];          // per-step grid-barrier flags

__device__ __forceinline__ float sigf(float x) { return 1.f / (1.f + __expf(-x)); }
__device__ __forceinline__ float tanhfast(float x) {
    float r; asm("tanh.approx.f32 %0, %1;" : "=f"(r) : "f"(x)); return r;
}
__device__ __forceinline__ unsigned tf32r(float x) {
    unsigned u; asm("cvt.rna.tf32.f32 %0, %1;" : "=r"(u) : "f"(x)); return u;
}

// m16n8k8 tf32 mma (row.col), D/C fp32
__device__ __forceinline__ void mma8(float* c, const unsigned* a, const unsigned* b) {
    asm volatile(
        "mma.sync.aligned.m16n8k8.row.col.f32.tf32.tf32.f32 "
        "{%0,%1,%2,%3}, {%4,%5,%6,%7}, {%8,%9}, {%0,%1,%2,%3};"
        : "+f"(c[0]), "+f"(c[1]), "+f"(c[2]), "+f"(c[3])
        : "r"(a[0]), "r"(a[1]), "r"(a[2]), "r"(a[3]), "r"(b[0]), "r"(b[1]));
}

// ---------------------------------------------------------------------------
// Tensor-core 3xTF32 GEMM (mma.sync): g_G[row][n] = X[row][:].W[n][:] + bias
// Block tile 128(M)x64(N), 8 warps (4Mx2N), warp tile 32x32, K chunks of 32.
// Smem: Ahi|Alo (128x36 u32), Bhi|Blo (64x36 u32) stride-36 => conflict-free
// fragment LDS. Register prefetch of next chunk across the MMA phase.
// ---------------------------------------------------------------------------
#define STRD 36
#define OF_AH 0
#define OF_AL (128 * STRD)
#define OF_BH (2 * 128 * STRD)
#define OF_BL (2 * 128 * STRD + 64 * STRD)
#define OF_BIAS (2 * 128 * STRD + 2 * 64 * STRD)          // floats (64)
#define GDYN ((OF_BIAS + 64) * 4)

__global__ __launch_bounds__(256, 2) void gemm_mma(
    const float* __restrict__ X, const float* __restrict__ W,
    const float* __restrict__ bi, const float* __restrict__ bh, int mode)
{
    extern __shared__ __align__(16) unsigned sm[];
    float* biasS = (float*)(sm + OF_BIAS);

    int tid = threadIdx.x, wid = tid >> 5, lane = tid & 31;
    int g = lane >> 2, tig = lane & 3;
    int bn = blockIdx.x, bm = blockIdx.y;
    int warpM = (wid >> 1) * 32, warpN = (wid & 1) * 32;

    if (tid < 64) biasS[tid] = bi[bn * 64 + tid] + bh[bn * 64 + tid];

    // producer mapping
    int ar = tid >> 1;                 // A row 0..127
    int ak = (tid & 1) * 16;           // A k-offset {0,16}
    int br = tid >> 2;                 // B row 0..63
    int bk = (tid & 3) * 8;            // B k-offset {0,8,16,24}

    const float* Xb = mode ? g_seq : X;
    int xrow = bm * 128 + ar;
    size_t xoff;
    if (mode == 0) { int t = xrow >> 5, b = xrow & 31; xoff = (size_t)b * (Sz * Hz) + (size_t)t * Hz; }
    else           { xoff = (size_t)xrow * Hz; }
    const float* xp = Xb + xoff + ak;
    const float* wp = W + (size_t)(bn * 64 + br) * Hz + bk;

    float acc[2][4][4];
#pragma unroll
    for (int mt = 0; mt < 2; mt++)
#pragma unroll
        for (int nt = 0; nt < 4; nt++)
#pragma unroll
            for (int r = 0; r < 4; r++) acc[mt][nt][r] = 0.f;

    float4 ra[4], rb[2];
#pragma unroll
    for (int j = 0; j < 4; j++) ra[j] = *(const float4*)(xp + 4 * j);
#pragma unroll
    for (int j = 0; j < 2; j++) rb[j] = *(const float4*)(wp + 4 * j);

    const int NCHUNK = Hz / 32;
    for (int i = 0; i < NCHUNK; i++) {
        // convert + store current chunk
#pragma unroll
        for (int j = 0; j < 4; j++) {
            float v[4] = { ra[j].x, ra[j].y, ra[j].z, ra[j].w };
#pragma unroll
            for (int e = 0; e < 4; e++) {
                unsigned hi = tf32r(v[e]);
                unsigned lo = tf32r(v[e] - __uint_as_float(hi));
                int kc = ak + 4 * j + e;
                sm[OF_AH + ar * STRD + kc] = hi;
                sm[OF_AL + ar * STRD + kc] = lo;
            }
        }
#pragma unroll
        for (int j = 0; j < 2; j++) {
            float v[4] = { rb[j].x, rb[j].y, rb[j].z, rb[j].w };
#pragma unroll
            for (int e = 0; e < 4; e++) {
                unsigned hi = tf32r(v[e]);
                unsigned lo = tf32r(v[e] - __uint_as_float(hi));
                int kc = bk + 4 * j + e;
                sm[OF_BH + br * STRD + kc] = hi;
                sm[OF_BL + br * STRD + kc] = lo;
            }
        }
        __syncthreads();

        if (i + 1 < NCHUNK) {          // prefetch next chunk (overlaps MMA)
#pragma unroll
            for (int j = 0; j < 4; j++) ra[j] = *(const float4*)(xp + (i + 1) * 32 + 4 * j);
#pragma unroll
            for (int j = 0; j < 2; j++) rb[j] = *(const float4*)(wp + (i + 1) * 32 + 4 * j);
        }

#pragma unroll
        for (int k8 = 0; k8 < 4; k8++) {
            unsigned Ah[2][4], Al[2][4];
#pragma unroll
            for (int mt = 0; mt < 2; mt++) {
                int base = (warpM + mt * 16 + g) * STRD + k8 * 8 + tig;
                Ah[mt][0] = sm[OF_AH + base];
                Ah[mt][1] = sm[OF_AH + base + 8 * STRD];
                Ah[mt][2] = sm[OF_AH + base + 4];
                Ah[mt][3] = sm[OF_AH + base + 8 * STRD + 4];
                Al[mt][0] = sm[OF_AL + base];
                Al[mt][1] = sm[OF_AL + base + 8 * STRD];
                Al[mt][2] = sm[OF_AL + base + 4];
                Al[mt][3] = sm[OF_AL + base + 8 * STRD + 4];
            }
#pragma unroll
            for (int nt = 0; nt < 4; nt++) {
                int bbase = (warpN + nt * 8 + g) * STRD + k8 * 8 + tig;
                unsigned Bh[2], Bl[2];
                Bh[0] = sm[OF_BH + bbase]; Bh[1] = sm[OF_BH + bbase + 4];
                Bl[0] = sm[OF_BL + bbase]; Bl[1] = sm[OF_BL + bbase + 4];
#pragma unroll
                for (int mt = 0; mt < 2; mt++) {
                    mma8(acc[mt][nt], Ah[mt], Bh);
                    mma8(acc[mt][nt], Ah[mt], Bl);
                    mma8(acc[mt][nt], Al[mt], Bh);
                }
            }
        }
        __syncthreads();
    }

    // epilogue: bias + store (c0,c1 are adjacent columns -> float2)
#pragma unroll
    for (int mt = 0; mt < 2; mt++) {
        int row0 = bm * 128 + warpM + mt * 16 + g;
#pragma unroll
        for (int nt = 0; nt < 4; nt++) {
            int cl = warpN + nt * 8 + tig * 2;
            int col = bn * 64 + cl;
            float b0 = biasS[cl], b1 = biasS[cl + 1];
            float* p0 = &g_G[(size_t)row0 * G4 + col];
            float* p1 = &g_G[(size_t)(row0 + 8) * G4 + col];
            *(float2*)p0 = make_float2(acc[mt][nt][0] + b0, acc[mt][nt][1] + b1);
            *(float2*)p1 = make_float2(acc[mt][nt][2] + b0, acc[mt][nt][3] + b1);
        }
    }
}

// ---------------------------------------------------------------------------
// Persistent recurrent kernel (unchanged from the passing round-3 version).
// ---------------------------------------------------------------------------
#define SM_W   (32 * 1024)
#define SM_H   (32 * 132)
#define SM_T   (32 * 33)
#define SMEMB  ((SM_W + SM_H + SM_T) * 4)

__global__ __launch_bounds__(256, 1) void lstm_persist(
    const float* __restrict__ Whh, float* __restrict__ out, int layer)
{
    extern __shared__ __align__(16) float smraw[];
    float* Wsm = smraw;
    float* hs  = smraw + SM_W;
    float* Ts  = smraw + SM_W + SM_H;

    int tid = threadIdx.x;
    int w = tid >> 5, lane = tid & 31;
    int u0 = blockIdx.x * 8;

    int lb = tid >> 3;
    int lk = (tid & 7) * 16;

    {
        int nl = (lb >> 3) * Hz + u0 + (lb & 7);
        const float* wpg = Whh + (size_t)nl * Hz + (tid & 7) * 128;
        float* dst = Wsm + lb * 1024 + (tid & 7) * 128;
#pragma unroll
        for (int i = 0; i < 128; i += 4)
            *(float4*)(dst + i) = *(const float4*)(wpg + i);
    }
    __syncthreads();

    float* cst = g_c + (size_t)layer * BH;
    unsigned* flags = g_flags + layer * Sz;

    const float* w0p = Wsm + (4 * w + 0) * 1024;
    const float* w1p = Wsm + (4 * w + 1) * 1024;
    const float* w2p = Wsm + (4 * w + 2) * 1024;
    const float* w3p = Wsm + (4 * w + 3) * 1024;
    const float* hsp = hs + lane * 132;

    for (int t = 0; t < Sz; t++) {
        const float* hprev = g_h + (size_t)(layer * 2 + (t & 1)) * BH;
        float* hnext       = g_h + (size_t)(layer * 2 + ((t + 1) & 1)) * BH;

        const float4* hp = (const float4*)(hprev + (size_t)lb * Hz + lk);
        float4 hr0 = __ldcg(hp + 0), hr1 = __ldcg(hp + 1),
               hr2 = __ldcg(hp + 2), hr3 = __ldcg(hp + 3);

        float4 s0 = {0,0,0,0}, s1 = {0,0,0,0}, s2 = {0,0,0,0}, s3 = {0,0,0,0};

        for (int k0 = 0; k0 < Hz; k0 += 128) {
            *(float4*)&hs[lb * 132 + lk]      = hr0;
            *(float4*)&hs[lb * 132 + lk + 4]  = hr1;
            *(float4*)&hs[lb * 132 + lk + 8]  = hr2;
            *(float4*)&hs[lb * 132 + lk + 12] = hr3;
            __syncthreads();
            if (k0 + 128 < Hz) {
                const float4* hp2 = hp + (k0 + 128) / 4;
                hr0 = __ldcg(hp2 + 0); hr1 = __ldcg(hp2 + 1);
                hr2 = __ldcg(hp2 + 2); hr3 = __ldcg(hp2 + 3);
            }
#pragma unroll 8
            for (int kk = 0; kk < 128; kk += 4) {
                float4 hv = *(const float4*)(hsp + kk);
                float4 a  = *(const float4*)(w0p + k0 + kk);
                float4 b  = *(const float4*)(w1p + k0 + kk);
                float4 c  = *(const float4*)(w2p + k0 + kk);
                float4 d  = *(const float4*)(w3p + k0 + kk);
                s0.x += hv.x * a.x; s0.y += hv.y * a.y; s0.z += hv.z * a.z; s0.w += hv.w * a.w;
                s1.x += hv.x * b.x; s1.y += hv.y * b.y; s1.z += hv.z * b.z; s1.w += hv.w * b.w;
                s2.x += hv.x * c.x; s2.y += hv.y * c.y; s2.z += hv.z * c.z; s2.w += hv.w * c.w;
                s3.x += hv.x * d.x; s3.y += hv.y * d.y; s3.z += hv.z * d.z; s3.w += hv.w * d.w;
            }
            __syncthreads();
        }

        Ts[(4 * w + 0) * 33 + lane] = s0.x + s0.y + s0.z + s0.w;
        Ts[(4 * w + 1) * 33 + lane] = s1.x + s1.y + s1.z + s1.w;
        Ts[(4 * w + 2) * 33 + lane] = s2.x + s2.y + s2.z + s2.w;
        Ts[(4 * w + 3) * 33 + lane] = s3.x + s3.y + s3.z + s3.w;
        __syncthreads();

        {
            int us = tid & 7, b = tid >> 3;
            int u = u0 + us;
            size_t grow = ((size_t)t * 32 + b) * G4;
            float pi = Ts[(us)      * 33 + b] + g_G[grow + u];
            float pf = Ts[(8 + us)  * 33 + b] + g_G[grow + Hz + u];
            float pg = Ts[(16 + us) * 33 + b] + g_G[grow + 2 * Hz + u];
            float po = Ts[(24 + us) * 33 + b] + g_G[grow + 3 * Hz + u];
            float co = cst[b * Hz + u];
            float ii = sigf(pi), ff = sigf(pf), gg = tanhfast(pg), oo = sigf(po);
            float cn = ff * co + ii * gg;
            float hn = oo * tanhfast(cn);
            cst[b * Hz + u] = cn;
            hnext[b * Hz + u] = hn;
            if (layer == 0) g_seq[((size_t)t * 32 + b) * Hz + u] = hn;
            else            out[(size_t)b * (Sz * Hz) + (size_t)t * Hz + u] = hn;
        }

        __threadfence();
        __syncthreads();
        if (tid == 0) {
            unsigned v = atomicAdd(&flags[t], 1u) + 1u;
            if (v < NBLK) {
                volatile unsigned* f = flags + t;
                while (*f < NBLK) __nanosleep(64);
            }
        }
        __syncthreads();
    }
}

// ---------------------------------------------------------------------------
__global__ void init_state(const float* __restrict__ h0, const float* __restrict__ c0)
{
    int i = blockIdx.x * 256 + threadIdx.x;
    if (i < Lz * BH) {
        int l = i >> 15;
        g_h[(l * 2 + 0) * BH + (i & 32767)] = h0[i];
        g_c[i] = c0[i];
    }
    if (i < Lz * Sz) g_flags[i] = 0u;
}

__global__ void write_tail(float* __restrict__ out)
{
    int i = blockIdx.x * 256 + threadIdx.x;
    if (i < Lz * BH) {
        int l = i >> 15;
        int r = i & 32767;
        out[MAIN + i] = g_h[(l * 2 + 0) * BH + r];
        out[MAIN + Lz * BH + i] = g_c[i];
    }
}

// ---------------------------------------------------------------------------
extern "C" void kernel_launch(void* const* d_in, const int* in_sizes, int n_in,
                              void* d_out, int out_size)
{
    const float* x   = (const float*)d_in[0];
    const float* h0  = (const float*)d_in[1];
    const float* c0  = (const float*)d_in[2];
    const float* Wih = (const float*)d_in[3];
    const float* Whh = (const float*)d_in[4];
    const float* bih = (const float*)d_in[5];
    const float* bhh = (const float*)d_in[6];
    float* out = (float*)d_out;

    cudaFuncSetAttribute(lstm_persist,
                         cudaFuncAttributeMaxDynamicSharedMemorySize, SMEMB);
    cudaFuncSetAttribute(gemm_mma,
                         cudaFuncAttributeMaxDynamicSharedMemorySize, GDYN);

    init_state<<<256, 256>>>(h0, c0);

    dim3 gg(G4 / 64, ROWS / 128);    // (64, 128)

    gemm_mma<<<gg, 256, GDYN>>>(x, Wih, bih, bhh, 0);
    lstm_persist<<<NBLK, 256, SMEMB>>>(Whh, out, 0);

    gemm_mma<<<gg, 256, GDYN>>>(x, Wih + 4 * Hz * Hz, bih + G4, bhh + G4, 1);
    lstm_persist<<<NBLK, 256, SMEMB>>>(Whh + 4 * Hz * Hz, out, 1);

    if (out_size >= MAIN + 2 * Lz * BH)
        write_tail<<<256, 256>>>(out);
}

// round 6
// speedup vs baseline: 1.0116x; 1.0116x over previous
#include <cuda_runtime.h>

// Problem constants
#define Bz 32
#define Sz 512
#define Hz 1024
#define Lz 2
#define G4 4096                 // 4*Hz
#define BH (Bz*Hz)              // 32768
#define ROWS (Sz*Bz)            // 16384
#define MAIN (Bz*Sz*Hz)         // 16777216
#define NBLK 128

// Static scratch (no runtime allocation allowed)
__device__ float    g_G[(size_t)ROWS * G4];    // x-projection + biases, [row=t*32+b][4H]
__device__ float    g_seq[(size_t)ROWS * Hz];  // layer-0 hidden outputs, [row][H]
__device__ float    g_h[Lz * 2 * BH];          // double-buffered h state per layer
__device__ float    g_c[Lz * BH];              // c state per layer
__device__ unsigned g_flags[Lz * Sz];          // per-step grid-barrier flags

__device__ __forceinline__ float sigf(float x) { return 1.f / (1.f + __expf(-x)); }
__device__ __forceinline__ float tanhfast(float x) {
    float r; asm("tanh.approx.f32 %0, %1;" : "=f"(r) : "f"(x)); return r;
}
__device__ __forceinline__ unsigned tf32r(float x) {
    unsigned u; asm("cvt.rna.tf32.f32 %0, %1;" : "=r"(u) : "f"(x)); return u;
}

// Packed dual-FMA on the fma pipe: d.lo += a.lo*b.lo, d.hi += a.hi*b.hi
__device__ __forceinline__ void fma2(unsigned long long& d,
                                     unsigned long long a, unsigned long long b) {
    asm("fma.rn.f32x2 %0, %1, %2, %0;" : "+l"(d) : "l"(a), "l"(b));
}
__device__ __forceinline__ float upk(unsigned long long v) {
    return __uint_as_float((unsigned)v) + __uint_as_float((unsigned)(v >> 32));
}

// m16n8k8 tf32 mma (row.col), D/C fp32
__device__ __forceinline__ void mma8(float* c, const unsigned* a, const unsigned* b) {
    asm volatile(
        "mma.sync.aligned.m16n8k8.row.col.f32.tf32.tf32.f32 "
        "{%0,%1,%2,%3}, {%4,%5,%6,%7}, {%8,%9}, {%0,%1,%2,%3};"
        : "+f"(c[0]), "+f"(c[1]), "+f"(c[2]), "+f"(c[3])
        : "r"(a[0]), "r"(a[1]), "r"(a[2]), "r"(a[3]), "r"(b[0]), "r"(b[1]));
}

// ---------------------------------------------------------------------------
// Tensor-core 3xTF32 GEMM (mma.sync) — unchanged from the round-5 PASS.
// ---------------------------------------------------------------------------
#define STRD 36
#define OF_AH 0
#define OF_AL (128 * STRD)
#define OF_BH (2 * 128 * STRD)
#define OF_BL (2 * 128 * STRD + 64 * STRD)
#define OF_BIAS (2 * 128 * STRD + 2 * 64 * STRD)
#define GDYN ((OF_BIAS + 64) * 4)

__global__ __launch_bounds__(256, 2) void gemm_mma(
    const float* __restrict__ X, const float* __restrict__ W,
    const float* __restrict__ bi, const float* __restrict__ bh, int mode)
{
    extern __shared__ __align__(16) unsigned sm[];
    float* biasS = (float*)(sm + OF_BIAS);

    int tid = threadIdx.x, wid = tid >> 5, lane = tid & 31;
    int g = lane >> 2, tig = lane & 3;
    int bn = blockIdx.x, bm = blockIdx.y;
    int warpM = (wid >> 1) * 32, warpN = (wid & 1) * 32;

    if (tid < 64) biasS[tid] = bi[bn * 64 + tid] + bh[bn * 64 + tid];

    int ar = tid >> 1;
    int ak = (tid & 1) * 16;
    int br = tid >> 2;
    int bk = (tid & 3) * 8;

    const float* Xb = mode ? g_seq : X;
    int xrow = bm * 128 + ar;
    size_t xoff;
    if (mode == 0) { int t = xrow >> 5, b = xrow & 31; xoff = (size_t)b * (Sz * Hz) + (size_t)t * Hz; }
    else           { xoff = (size_t)xrow * Hz; }
    const float* xp = Xb + xoff + ak;
    const float* wp = W + (size_t)(bn * 64 + br) * Hz + bk;

    float acc[2][4][4];
#pragma unroll
    for (int mt = 0; mt < 2; mt++)
#pragma unroll
        for (int nt = 0; nt < 4; nt++)
#pragma unroll
            for (int r = 0; r < 4; r++) acc[mt][nt][r] = 0.f;

    float4 ra[4], rb[2];
#pragma unroll
    for (int j = 0; j < 4; j++) ra[j] = *(const float4*)(xp + 4 * j);
#pragma unroll
    for (int j = 0; j < 2; j++) rb[j] = *(const float4*)(wp + 4 * j);

    const int NCHUNK = Hz / 32;
    for (int i = 0; i < NCHUNK; i++) {
#pragma unroll
        for (int j = 0; j < 4; j++) {
            float v[4] = { ra[j].x, ra[j].y, ra[j].z, ra[j].w };
#pragma unroll
            for (int e = 0; e < 4; e++) {
                unsigned hi = tf32r(v[e]);
                unsigned lo = tf32r(v[e] - __uint_as_float(hi));
                int kc = ak + 4 * j + e;
                sm[OF_AH + ar * STRD + kc] = hi;
                sm[OF_AL + ar * STRD + kc] = lo;
            }
        }
#pragma unroll
        for (int j = 0; j < 2; j++) {
            float v[4] = { rb[j].x, rb[j].y, rb[j].z, rb[j].w };
#pragma unroll
            for (int e = 0; e < 4; e++) {
                unsigned hi = tf32r(v[e]);
                unsigned lo = tf32r(v[e] - __uint_as_float(hi));
                int kc = bk + 4 * j + e;
                sm[OF_BH + br * STRD + kc] = hi;
                sm[OF_BL + br * STRD + kc] = lo;
            }
        }
        __syncthreads();

        if (i + 1 < NCHUNK) {
#pragma unroll
            for (int j = 0; j < 4; j++) ra[j] = *(const float4*)(xp + (i + 1) * 32 + 4 * j);
#pragma unroll
            for (int j = 0; j < 2; j++) rb[j] = *(const float4*)(wp + (i + 1) * 32 + 4 * j);
        }

#pragma unroll
        for (int k8 = 0; k8 < 4; k8++) {
            unsigned Ah[2][4], Al[2][4];
#pragma unroll
            for (int mt = 0; mt < 2; mt++) {
                int base = (warpM + mt * 16 + g) * STRD + k8 * 8 + tig;
                Ah[mt][0] = sm[OF_AH + base];
                Ah[mt][1] = sm[OF_AH + base + 8 * STRD];
                Ah[mt][2] = sm[OF_AH + base + 4];
                Ah[mt][3] = sm[OF_AH + base + 8 * STRD + 4];
                Al[mt][0] = sm[OF_AL + base];
                Al[mt][1] = sm[OF_AL + base + 8 * STRD];
                Al[mt][2] = sm[OF_AL + base + 4];
                Al[mt][3] = sm[OF_AL + base + 8 * STRD + 4];
            }
#pragma unroll
            for (int nt = 0; nt < 4; nt++) {
                int bbase = (warpN + nt * 8 + g) * STRD + k8 * 8 + tig;
                unsigned Bh[2], Bl[2];
                Bh[0] = sm[OF_BH + bbase]; Bh[1] = sm[OF_BH + bbase + 4];
                Bl[0] = sm[OF_BL + bbase]; Bl[1] = sm[OF_BL + bbase + 4];
#pragma unroll
                for (int mt = 0; mt < 2; mt++) {
                    mma8(acc[mt][nt], Ah[mt], Bh);
                    mma8(acc[mt][nt], Ah[mt], Bl);
                    mma8(acc[mt][nt], Al[mt], Bh);
                }
            }
        }
        __syncthreads();
    }

#pragma unroll
    for (int mt = 0; mt < 2; mt++) {
        int row0 = bm * 128 + warpM + mt * 16 + g;
#pragma unroll
        for (int nt = 0; nt < 4; nt++) {
            int cl = warpN + nt * 8 + tig * 2;
            int col = bn * 64 + cl;
            float b0 = biasS[cl], b1 = biasS[cl + 1];
            float* p0 = &g_G[(size_t)row0 * G4 + col];
            float* p1 = &g_G[(size_t)(row0 + 8) * G4 + col];
            *(float2*)p0 = make_float2(acc[mt][nt][0] + b0, acc[mt][nt][1] + b1);
            *(float2*)p1 = make_float2(acc[mt][nt][2] + b0, acc[mt][nt][3] + b1);
        }
    }
}

// ---------------------------------------------------------------------------
// Persistent recurrent kernel — same structure as the round-3/5 PASS, but the
// inner dot products use packed fma.rn.f32x2 (FFMA2): half the fma-pipe
// issues for identical fp32 math.
// ---------------------------------------------------------------------------
#define SM_W   (32 * 1024)
#define SM_H   (32 * 132)
#define SM_T   (32 * 33)
#define SMEMB  ((SM_W + SM_H + SM_T) * 4)

__global__ __launch_bounds__(256, 1) void lstm_persist(
    const float* __restrict__ Whh, float* __restrict__ out, int layer)
{
    extern __shared__ __align__(16) float smraw[];
    float* Wsm = smraw;
    float* hs  = smraw + SM_W;
    float* Ts  = smraw + SM_W + SM_H;

    int tid = threadIdx.x;
    int w = tid >> 5, lane = tid & 31;
    int u0 = blockIdx.x * 8;

    int lb = tid >> 3;
    int lk = (tid & 7) * 16;

    {
        int nl = (lb >> 3) * Hz + u0 + (lb & 7);
        const float* wpg = Whh + (size_t)nl * Hz + (tid & 7) * 128;
        float* dst = Wsm + lb * 1024 + (tid & 7) * 128;
#pragma unroll
        for (int i = 0; i < 128; i += 4)
            *(float4*)(dst + i) = *(const float4*)(wpg + i);
    }
    __syncthreads();

    float* cst = g_c + (size_t)layer * BH;
    unsigned* flags = g_flags + layer * Sz;

    const float* w0p = Wsm + (4 * w + 0) * 1024;
    const float* w1p = Wsm + (4 * w + 1) * 1024;
    const float* w2p = Wsm + (4 * w + 2) * 1024;
    const float* w3p = Wsm + (4 * w + 3) * 1024;
    const float* hsp = hs + lane * 132;

    for (int t = 0; t < Sz; t++) {
        const float* hprev = g_h + (size_t)(layer * 2 + (t & 1)) * BH;
        float* hnext       = g_h + (size_t)(layer * 2 + ((t + 1) & 1)) * BH;

        const float4* hp = (const float4*)(hprev + (size_t)lb * Hz + lk);
        float4 hr0 = __ldcg(hp + 0), hr1 = __ldcg(hp + 1),
               hr2 = __ldcg(hp + 2), hr3 = __ldcg(hp + 3);

        // packed accumulators: [gate][pair-half]
        unsigned long long a0 = 0ull, a1 = 0ull, a2 = 0ull, a3 = 0ull;
        unsigned long long b0 = 0ull, b1 = 0ull, b2 = 0ull, b3 = 0ull;

        for (int k0 = 0; k0 < Hz; k0 += 128) {
            *(float4*)&hs[lb * 132 + lk]      = hr0;
            *(float4*)&hs[lb * 132 + lk + 4]  = hr1;
            *(float4*)&hs[lb * 132 + lk + 8]  = hr2;
            *(float4*)&hs[lb * 132 + lk + 12] = hr3;
            __syncthreads();
            if (k0 + 128 < Hz) {
                const float4* hp2 = hp + (k0 + 128) / 4;
                hr0 = __ldcg(hp2 + 0); hr1 = __ldcg(hp2 + 1);
                hr2 = __ldcg(hp2 + 2); hr3 = __ldcg(hp2 + 3);
            }
#pragma unroll 8
            for (int kk = 0; kk < 128; kk += 4) {
                ulonglong2 hv = *(const ulonglong2*)(hsp + kk);
                ulonglong2 wa = *(const ulonglong2*)(w0p + k0 + kk);
                ulonglong2 wb = *(const ulonglong2*)(w1p + k0 + kk);
                ulonglong2 wc = *(const ulonglong2*)(w2p + k0 + kk);
                ulonglong2 wd = *(const ulonglong2*)(w3p + k0 + kk);
                fma2(a0, hv.x, wa.x); fma2(a1, hv.y, wa.y);
                fma2(b0, hv.x, wb.x); fma2(b1, hv.y, wb.y);
                fma2(a2, hv.x, wc.x); fma2(a3, hv.y, wc.y);
                fma2(b2, hv.x, wd.x); fma2(b3, hv.y, wd.y);
            }
            __syncthreads();
        }

        Ts[(4 * w + 0) * 33 + lane] = upk(a0) + upk(a1);
        Ts[(4 * w + 1) * 33 + lane] = upk(b0) + upk(b1);
        Ts[(4 * w + 2) * 33 + lane] = upk(a2) + upk(a3);
        Ts[(4 * w + 3) * 33 + lane] = upk(b2) + upk(b3);
        __syncthreads();

        {
            int us = tid & 7, b = tid >> 3;
            int u = u0 + us;
            size_t grow = ((size_t)t * 32 + b) * G4;
            float pi = Ts[(us)      * 33 + b] + g_G[grow + u];
            float pf = Ts[(8 + us)  * 33 + b] + g_G[grow + Hz + u];
            float pg = Ts[(16 + us) * 33 + b] + g_G[grow + 2 * Hz + u];
            float po = Ts[(24 + us) * 33 + b] + g_G[grow + 3 * Hz + u];
            float co = cst[b * Hz + u];
            float ii = sigf(pi), ff = sigf(pf), gg = tanhfast(pg), oo = sigf(po);
            float cn = ff * co + ii * gg;
            float hn = oo * tanhfast(cn);
            cst[b * Hz + u] = cn;
            hnext[b * Hz + u] = hn;
            if (layer == 0) g_seq[((size_t)t * 32 + b) * Hz + u] = hn;
            else            out[(size_t)b * (Sz * Hz) + (size_t)t * Hz + u] = hn;
        }

        __threadfence();
        __syncthreads();
        if (tid == 0) {
            unsigned v = atomicAdd(&flags[t], 1u) + 1u;
            if (v < NBLK) {
                volatile unsigned* f = flags + t;
                while (*f < NBLK) __nanosleep(64);
            }
        }
        __syncthreads();
    }
}

// ---------------------------------------------------------------------------
__global__ void init_state(const float* __restrict__ h0, const float* __restrict__ c0)
{
    int i = blockIdx.x * 256 + threadIdx.x;
    if (i < Lz * BH) {
        int l = i >> 15;
        g_h[(l * 2 + 0) * BH + (i & 32767)] = h0[i];
        g_c[i] = c0[i];
    }
    if (i < Lz * Sz) g_flags[i] = 0u;
}

__global__ void write_tail(float* __restrict__ out)
{
    int i = blockIdx.x * 256 + threadIdx.x;
    if (i < Lz * BH) {
        int l = i >> 15;
        int r = i & 32767;
        out[MAIN + i] = g_h[(l * 2 + 0) * BH + r];
        out[MAIN + Lz * BH + i] = g_c[i];
    }
}

// ---------------------------------------------------------------------------
extern "C" void kernel_launch(void* const* d_in, const int* in_sizes, int n_in,
                              void* d_out, int out_size)
{
    const float* x   = (const float*)d_in[0];
    const float* h0  = (const float*)d_in[1];
    const float* c0  = (const float*)d_in[2];
    const float* Wih = (const float*)d_in[3];
    const float* Whh = (const float*)d_in[4];
    const float* bih = (const float*)d_in[5];
    const float* bhh = (const float*)d_in[6];
    float* out = (float*)d_out;

    cudaFuncSetAttribute(lstm_persist,
                         cudaFuncAttributeMaxDynamicSharedMemorySize, SMEMB);
    cudaFuncSetAttribute(gemm_mma,
                         cudaFuncAttributeMaxDynamicSharedMemorySize, GDYN);

    init_state<<<256, 256>>>(h0, c0);

    dim3 gg(G4 / 64, ROWS / 128);    // (64, 128)

    gemm_mma<<<gg, 256, GDYN>>>(x, Wih, bih, bhh, 0);
    lstm_persist<<<NBLK, 256, SMEMB>>>(Whh, out, 0);

    gemm_mma<<<gg, 256, GDYN>>>(x, Wih + 4 * Hz * Hz, bih + G4, bhh + G4, 1);
    lstm_persist<<<NBLK, 256, SMEMB>>>(Whh + 4 * Hz * Hz, out, 1);

    if (out_size >= MAIN + 2 * Lz * BH)
        write_tail<<<256, 256>>>(out);
}